// round 1
// baseline (speedup 1.0000x reference)
#include <cuda_runtime.h>

#define Bc 4
#define Nc 8192
#define Cc 64
#define Kc 16
#define BN_SCALE_F 0.9999950000374997f

// folded-weight slab layout (floats), per block
#define FOLD_FLOATS 16896
#define OFF_W1   0      // float2[3][32]   (192 floats)
#define OFF_B1   192
#define OFF_W2   256    // float2[64][32]  (4096 floats)
#define OFF_B2   4352
#define OFF_A1   4416
#define OFF_AB1  8512
#define OFF_A2   8576
#define OFF_AB2  12672
#define OFF_DW   12736
#define OFF_DB   16832

#define VSTRIDE 20
#define VWARP   (64*VSTRIDE)   // 1280 floats per warp
#define NWARPS  8
#define SMEM_FLOATS (FOLD_FLOATS + NWARPS*VWARP + NWARPS*16)

__device__ float  g_fold[2*FOLD_FLOATS];
__device__ float4 g_p4[Bc*Nc];
__device__ float  g_xA[Bc*Nc*Cc];
__device__ float  g_xB[Bc*Nc*Cc];

struct WPtrs { const float* p[20]; };

// ---------------- weight folding (BN folded into linear) ----------------
__device__ __forceinline__ void foldCC(float* F, int offW, int offB,
                                       const float* W, const float* bv,
                                       const float* g, const float* be,
                                       int blk, int o) {
  float gs = g[blk*64+o]*BN_SCALE_F;
  const float* Wr = W + blk*4096 + o*64;
  int sel = o>>5, l = o&31;
  for (int j = 0; j < 64; j++)
    F[offW + (j*32+l)*2 + sel] = Wr[j]*gs;
  F[offB+o] = bv[blk*64+o]*gs + be[blk*64+o];
}

__global__ void fold_kernel(WPtrs wp) {
  int blk = blockIdx.x, o = threadIdx.x;  // grid 2, block 64
  float* F = g_fold + blk*FOLD_FLOATS;
  {
    float gs = wp.p[2][blk*64+o]*BN_SCALE_F;
    int sel = o>>5, l = o&31;
    for (int j = 0; j < 3; j++)
      F[OFF_W1 + (j*32+l)*2 + sel] = wp.p[0][blk*64*3 + o*3 + j]*gs;
    F[OFF_B1+o] = wp.p[1][blk*64+o]*gs + wp.p[3][blk*64+o];
  }
  foldCC(F, OFF_W2, OFF_B2,  wp.p[4],  wp.p[5],  wp.p[6],  wp.p[7],  blk, o);
  foldCC(F, OFF_A1, OFF_AB1, wp.p[8],  wp.p[9],  wp.p[10], wp.p[11], blk, o);
  foldCC(F, OFF_A2, OFF_AB2, wp.p[12], wp.p[13], wp.p[14], wp.p[15], blk, o);
  foldCC(F, OFF_DW, OFF_DB,  wp.p[16], wp.p[17], wp.p[18], wp.p[19], blk, o);
}

// ---------------- pack p [B,3,N] -> float4 [B*N] ----------------
__global__ void pack_p_kernel(const float* __restrict__ p) {
  int t = blockIdx.x*blockDim.x + threadIdx.x;
  if (t < Bc*Nc) {
    int b = t >> 13, n = t & (Nc-1);
    const float* pb = p + (size_t)b*3*Nc;
    g_p4[t] = make_float4(pb[n], pb[Nc+n], pb[2*Nc+n], 0.f);
  }
}

// ---------------- transpose x [B,C,N] -> [B,N,C] ----------------
__global__ void trans_x_kernel(const float* __restrict__ x) {
  __shared__ float t[32][33];
  int b = blockIdx.z;
  int n0 = blockIdx.x*32, c0 = blockIdx.y*32;
  int tx = threadIdx.x, ty = threadIdx.y;  // 32x8
  for (int i = ty; i < 32; i += 8)
    t[i][tx] = x[(size_t)b*Cc*Nc + (size_t)(c0+i)*Nc + n0 + tx];
  __syncthreads();
  for (int i = ty; i < 32; i += 8)
    g_xA[(size_t)b*Nc*Cc + (size_t)(n0+i)*Cc + c0 + tx] = t[tx][i];
}

// ---------------- helpers ----------------
__device__ __forceinline__ void store_v(float* v, int lane,
                                        const float a0[16], const float a1[16]) {
  float* r0 = v + lane*VSTRIDE;
  float* r1 = v + (lane+32)*VSTRIDE;
#pragma unroll
  for (int kq = 0; kq < 4; kq++) {
    *(float4*)(r0 + kq*4) = make_float4(a0[kq*4], a0[kq*4+1], a0[kq*4+2], a0[kq*4+3]);
    *(float4*)(r1 + kq*4) = make_float4(a1[kq*4], a1[kq*4+1], a1[kq*4+2], a1[kq*4+3]);
  }
}

__device__ __forceinline__ void matvec64(const float2* __restrict__ W,
                                         const float* __restrict__ bias,
                                         const float* __restrict__ v, int lane,
                                         float a0[16], float a1[16]) {
  float b0 = bias[lane], b1 = bias[lane+32];
#pragma unroll
  for (int k = 0; k < 16; k++) { a0[k] = b0; a1[k] = b1; }
#pragma unroll 4
  for (int j = 0; j < 64; j++) {
    float2 w = W[j*32 + lane];
    const float* vr = v + j*VSTRIDE;
    float4 va = *(const float4*)(vr);
    float4 vb = *(const float4*)(vr + 4);
    float4 vc = *(const float4*)(vr + 8);
    float4 vd = *(const float4*)(vr + 12);
    a0[0]  = fmaf(w.x, va.x, a0[0]);  a0[1]  = fmaf(w.x, va.y, a0[1]);
    a0[2]  = fmaf(w.x, va.z, a0[2]);  a0[3]  = fmaf(w.x, va.w, a0[3]);
    a0[4]  = fmaf(w.x, vb.x, a0[4]);  a0[5]  = fmaf(w.x, vb.y, a0[5]);
    a0[6]  = fmaf(w.x, vb.z, a0[6]);  a0[7]  = fmaf(w.x, vb.w, a0[7]);
    a0[8]  = fmaf(w.x, vc.x, a0[8]);  a0[9]  = fmaf(w.x, vc.y, a0[9]);
    a0[10] = fmaf(w.x, vc.z, a0[10]); a0[11] = fmaf(w.x, vc.w, a0[11]);
    a0[12] = fmaf(w.x, vd.x, a0[12]); a0[13] = fmaf(w.x, vd.y, a0[13]);
    a0[14] = fmaf(w.x, vd.z, a0[14]); a0[15] = fmaf(w.x, vd.w, a0[15]);
    a1[0]  = fmaf(w.y, va.x, a1[0]);  a1[1]  = fmaf(w.y, va.y, a1[1]);
    a1[2]  = fmaf(w.y, va.z, a1[2]);  a1[3]  = fmaf(w.y, va.w, a1[3]);
    a1[4]  = fmaf(w.y, vb.x, a1[4]);  a1[5]  = fmaf(w.y, vb.y, a1[5]);
    a1[6]  = fmaf(w.y, vb.z, a1[6]);  a1[7]  = fmaf(w.y, vb.w, a1[7]);
    a1[8]  = fmaf(w.y, vc.x, a1[8]);  a1[9]  = fmaf(w.y, vc.y, a1[9]);
    a1[10] = fmaf(w.y, vc.z, a1[10]); a1[11] = fmaf(w.y, vc.w, a1[11]);
    a1[12] = fmaf(w.y, vd.x, a1[12]); a1[13] = fmaf(w.y, vd.y, a1[13]);
    a1[14] = fmaf(w.y, vd.z, a1[14]); a1[15] = fmaf(w.y, vd.w, a1[15]);
  }
}

// ---------------- fused PT block: warp-per-point, K=16 GEMM style ----------------
__global__ void __launch_bounds__(256) trblock_kernel(
    const int* __restrict__ idx, int blk, int finalOut, float* __restrict__ dout) {
  const float* __restrict__ xin = blk ? g_xB : g_xA;
  extern __shared__ float S[];
  int tid = threadIdx.x, wid = tid >> 5, lane = tid & 31;

  // cache folded weights in shared (same layout as g_fold slab)
  const float* F = g_fold + blk*FOLD_FLOATS;
  for (int i = tid; i < FOLD_FLOATS; i += 256) S[i] = F[i];
  __syncthreads();

  float* v  = S + FOLD_FLOATS + wid*VWARP;
  int*   nb = (int*)(S + FOLD_FLOATS + NWARPS*VWARP) + wid*16;

  const float2* w1p = (const float2*)(S + OFF_W1);
  const float2* w2p = (const float2*)(S + OFF_W2);
  const float2* a1p = (const float2*)(S + OFF_A1);
  const float2* a2p = (const float2*)(S + OFF_A2);
  const float2* dwp = (const float2*)(S + OFF_DW);

  int gw = blockIdx.x*NWARPS + wid;
  int tw = gridDim.x*NWARPS;

  for (int pt = gw; pt < Bc*Nc; pt += tw) {
    int b = pt >> 13, n = pt & (Nc-1);
    __syncwarp();
    if (lane < 16) {
      int j = idx[(size_t)(b*Nc + n)*Kc + lane];
      nb[lane] = j;
      float4 pq = g_p4[b*Nc + n];
      float4 pn = g_p4[b*Nc + j];
      v[0*VSTRIDE + lane] = pq.x - pn.x;
      v[1*VSTRIDE + lane] = pq.y - pn.y;
      v[2*VSTRIDE + lane] = pq.z - pn.z;
    }
    __syncwarp();

    float a0[16], a1[16];
    // ---- stage 1: delta layer1 (3 -> 64), BN folded, relu ----
    {
      float b0 = S[OFF_B1 + lane], b1v = S[OFF_B1 + lane + 32];
#pragma unroll
      for (int k = 0; k < 16; k++) { a0[k] = b0; a1[k] = b1v; }
#pragma unroll
      for (int j = 0; j < 3; j++) {
        float2 w = w1p[j*32 + lane];
#pragma unroll
        for (int kq = 0; kq < 4; kq++) {
          float4 vv = *(const float4*)(v + j*VSTRIDE + kq*4);
          a0[kq*4+0] = fmaf(w.x, vv.x, a0[kq*4+0]);
          a0[kq*4+1] = fmaf(w.x, vv.y, a0[kq*4+1]);
          a0[kq*4+2] = fmaf(w.x, vv.z, a0[kq*4+2]);
          a0[kq*4+3] = fmaf(w.x, vv.w, a0[kq*4+3]);
          a1[kq*4+0] = fmaf(w.y, vv.x, a1[kq*4+0]);
          a1[kq*4+1] = fmaf(w.y, vv.y, a1[kq*4+1]);
          a1[kq*4+2] = fmaf(w.y, vv.z, a1[kq*4+2]);
          a1[kq*4+3] = fmaf(w.y, vv.w, a1[kq*4+3]);
        }
      }
#pragma unroll
      for (int k = 0; k < 16; k++) { a0[k] = fmaxf(a0[k], 0.f); a1[k] = fmaxf(a1[k], 0.f); }
    }
    __syncwarp(); store_v(v, lane, a0, a1); __syncwarp();

    // ---- stage 2: delta layer2 (64 -> 64), no relu -> pe ----
    matvec64(w2p, S + OFF_B2, v, lane, a0, a1);

    // ---- u = gx + pe (gather of transposed x, coalesced, L2-resident) ----
    {
      const float* xb = xin + (size_t)b*Nc*Cc;
#pragma unroll
      for (int k = 0; k < 16; k++) {
        int j = nb[k];
        a0[k] += xb[j*Cc + lane];
        a1[k] += xb[j*Cc + lane + 32];
      }
    }
    __syncwarp(); store_v(v, lane, a0, a1); __syncwarp();

    // ---- alpha layer1 (relu) ----
    matvec64(a1p, S + OFF_AB1, v, lane, a0, a1);
#pragma unroll
    for (int k = 0; k < 16; k++) { a0[k] = fmaxf(a0[k], 0.f); a1[k] = fmaxf(a1[k], 0.f); }
    __syncwarp(); store_v(v, lane, a0, a1); __syncwarp();

    // ---- alpha layer2, relu fused into max over K ----
    matvec64(a2p, S + OFF_AB2, v, lane, a0, a1);
    float m0 = 0.f, m1 = 0.f;
#pragma unroll
    for (int k = 0; k < 16; k++) { m0 = fmaxf(m0, a0[k]); m1 = fmaxf(m1, a1[k]); }

    // ---- down projection (64 -> 64) + residual ----
    __syncwarp();
    v[lane*VSTRIDE]      = m0;
    v[(lane+32)*VSTRIDE] = m1;
    __syncwarp();
    float o0 = S[OFF_DB + lane], o1 = S[OFF_DB + lane + 32];
#pragma unroll 16
    for (int j = 0; j < 64; j++) {
      float2 w = dwp[j*32 + lane];
      float y = v[j*VSTRIDE];
      o0 = fmaf(w.x, y, o0);
      o1 = fmaf(w.y, y, o1);
    }
    const float* xr = xin + ((size_t)b*Nc + n)*Cc;
    o0 += xr[lane];
    o1 += xr[lane + 32];

    if (finalOut) {
      dout[(size_t)b*Cc*Nc + (size_t)lane*Nc + n]      = o0;
      dout[(size_t)b*Cc*Nc + (size_t)(lane+32)*Nc + n] = o1;
    } else {
      float* xo = g_xB + ((size_t)b*Nc + n)*Cc;
      xo[lane]      = o0;
      xo[lane + 32] = o1;
    }
  }
}

// ---------------- launch ----------------
extern "C" void kernel_launch(void* const* d_in, const int* in_sizes, int n_in,
                              void* d_out, int out_size) {
  const float* p  = (const float*)d_in[0];
  const float* x  = (const float*)d_in[1];
  const int*  idx = (const int*)d_in[2];
  WPtrs w;
  for (int i = 0; i < 20; i++) w.p[i] = (const float*)d_in[3 + i];

  fold_kernel<<<2, 64>>>(w);
  pack_p_kernel<<<(Bc*Nc + 255)/256, 256>>>(p);
  trans_x_kernel<<<dim3(Nc/32, Cc/32, Bc), dim3(32, 8)>>>(x);

  size_t smem = SMEM_FLOATS * sizeof(float);
  cudaFuncSetAttribute(trblock_kernel, cudaFuncAttributeMaxDynamicSharedMemorySize, (int)smem);

  float* dout = (float*)d_out;
  trblock_kernel<<<296, 256, smem>>>(idx, 0, 0, nullptr);
  trblock_kernel<<<296, 256, smem>>>(idx, 1, 1, dout + (size_t)Bc*3*Nc);

  // first output: p passes through unchanged
  cudaMemcpyAsync(d_out, d_in[0], (size_t)Bc*3*Nc*sizeof(float),
                  cudaMemcpyDeviceToDevice);
}